// round 1
// baseline (speedup 1.0000x reference)
#include <cuda_runtime.h>

// ---- problem constants ----
#define BATCH 8
#define HH    112
#define WWID  112
#define DIM   192
#define HEADS 6
#define HD    32
#define WS    7
#define WA    49
#define EXPAND 3
#define NWH   16
#define NWW   16
#define BNW   2048           // BATCH * 256 windows
#define NROLL 132
#define NK    230            // 49 own + 132 rolled + 49 pooled
#define QKVC  (3*DIM)        // 576
#define ATT_SCALE 0.17677669529663689f  // 32^-0.5

// ---- scratch (device globals: allocation-free) ----
__device__ float g_qkv [BATCH*HH*WWID*QKVC];     // (B,112,112,576)
__device__ float g_qkvp[BATCH*NWH*NWW*QKVC];     // (B,16,16,576)
__device__ float g_attnout[BNW*WA*DIM];          // (2048,49,192)
__device__ int   g_rtab[NROLL];                  // packed (s<<6)|(r<<3)|c

// ============================================================
// init: rolled-ring valid-index table (matches VALID_ROLLED order)
// ============================================================
__global__ void init_rtab_kernel() {
    if (threadIdx.x == 0 && blockIdx.x == 0) {
        int n = 0;
        for (int s = 0; s < 4; s++)
            for (int r = 0; r < 7; r++)
                for (int c = 0; c < 7; c++) {
                    bool inval;
                    if      (s == 0) inval = (r < 4 && c < 4);
                    else if (s == 1) inval = (r < 4 && c >= 3);
                    else if (s == 2) inval = (r >= 3 && c < 4);
                    else             inval = (r >= 3 && c >= 3);
                    if (!inval) g_rtab[n++] = (s << 6) | (r << 3) | c;
                }
    }
}

// ============================================================
// GEMM: C[M,N] = A[M,K] @ Bw[N,K]^T + bias[N]
// 64x64 tile, k-chunk 16, 256 threads, 4x4 per thread.
// M,N multiples of 64; K multiple of 16 (true for all our calls).
// ============================================================
__global__ __launch_bounds__(256)
void gemm_bias_kernel(const float* __restrict__ A, const float* __restrict__ Bw,
                      const float* __restrict__ bias, float* __restrict__ C,
                      int M, int N, int K) {
    __shared__ float As[16][68];
    __shared__ float Bs[16][68];
    const int tid = threadIdx.x;
    const int m0 = blockIdx.x << 6;
    const int n0 = blockIdx.y << 6;
    const int lr = tid >> 2;            // 0..63 row of tile
    const int lq = (tid & 3) << 2;      // k-quad 0,4,8,12
    const int tx = tid & 15, ty = tid >> 4;

    float acc[4][4] = {};

    for (int k0 = 0; k0 < K; k0 += 16) {
        float4 av = *(const float4*)(A  + (long)(m0 + lr) * K + k0 + lq);
        float4 bv = *(const float4*)(Bw + (long)(n0 + lr) * K + k0 + lq);
        As[lq + 0][lr] = av.x; As[lq + 1][lr] = av.y;
        As[lq + 2][lr] = av.z; As[lq + 3][lr] = av.w;
        Bs[lq + 0][lr] = bv.x; Bs[lq + 1][lr] = bv.y;
        Bs[lq + 2][lr] = bv.z; Bs[lq + 3][lr] = bv.w;
        __syncthreads();
#pragma unroll
        for (int kk = 0; kk < 16; kk++) {
            float4 a4 = *(const float4*)&As[kk][ty << 2];
            float4 b4 = *(const float4*)&Bs[kk][tx << 2];
            float a[4] = {a4.x, a4.y, a4.z, a4.w};
            float b[4] = {b4.x, b4.y, b4.z, b4.w};
#pragma unroll
            for (int i = 0; i < 4; i++)
#pragma unroll
                for (int j = 0; j < 4; j++)
                    acc[i][j] += a[i] * b[j];
        }
        __syncthreads();
    }

    float4 bb = *(const float4*)(bias + n0 + (tx << 2));
#pragma unroll
    for (int i = 0; i < 4; i++) {
        float4 o;
        o.x = acc[i][0] + bb.x; o.y = acc[i][1] + bb.y;
        o.z = acc[i][2] + bb.z; o.w = acc[i][3] + bb.w;
        *(float4*)(C + (long)(m0 + (ty << 2) + i) * N + n0 + (tx << 2)) = o;
    }
}

// ============================================================
// attention: one block = one (window, head). 256 threads.
// smem: q(49x32) k(230x32) v(230x32) logits(49x230) = 110232 B
// ============================================================
__global__ __launch_bounds__(256)
void attn_kernel(const float* __restrict__ rpb_table,
                 const float* __restrict__ rpb_nb,
                 const float* __restrict__ rpb_win) {
    extern __shared__ float sm[];
    float* sq = sm;                    // WA*HD
    float* sk = sq + WA * HD;          // NK*HD
    float* sv = sk + NK * HD;          // NK*HD
    float* sl = sv + NK * HD;          // WA*NK

    const int tid = threadIdx.x;
    const int w = blockIdx.x;          // 0..2047
    const int h = blockIdx.y;          // 0..5
    const int b  = w >> 8;
    const int wl = w & 255;
    const int wi = wl >> 4, wj = wl & 15;
    const int y0 = wi * WS, x0 = wj * WS;

    // ---- load q (scaled) ----
    for (int i = tid; i < WA * HD; i += 256) {
        int qi = i >> 5, d = i & 31;
        int r = qi / 7, c = qi - r * 7;
        sq[i] = g_qkv[(((b * HH) + (y0 + r)) * WWID + (x0 + c)) * QKVC + h * HD + d] * ATT_SCALE;
    }

    // ---- gather k / v (own window, rolled ring, pooled unfold) ----
    for (int i = tid; i < NK * HD; i += 256) {
        int j = i >> 5, d = i & 31;
        float kv = 0.f, vv = 0.f;
        if (j < WA) {
            int r = j / 7, c = j - r * 7;
            int base = (((b * HH) + (y0 + r)) * WWID + (x0 + c)) * QKVC;
            kv = g_qkv[base + DIM     + h * HD + d];
            vv = g_qkv[base + 2 * DIM + h * HD + d];
        } else if (j < WA + NROLL) {
            int pk = g_rtab[j - WA];
            int s = pk >> 6, r = (pk >> 3) & 7, c = pk & 7;
            int dy = (s < 2) ? EXPAND : -EXPAND;          // roll source offset
            int dx = ((s & 1) == 0) ? EXPAND : -EXPAND;
            int y = (y0 + r + dy + HH) % HH;
            int x = (x0 + c + dx + WWID) % WWID;
            int base = ((b * HH + y) * WWID + x) * QKVC;
            kv = g_qkv[base + DIM     + h * HD + d];
            vv = g_qkv[base + 2 * DIM + h * HD + d];
        } else {
            int jp = j - WA - NROLL;
            int r = jp / 7, c = jp - r * 7;
            int py = wi + r - EXPAND, px = wj + c - EXPAND;
            if (py >= 0 && py < NWH && px >= 0 && px < NWW) {
                int base = ((b * NWH + py) * NWW + px) * QKVC;
                kv = g_qkvp[base + DIM     + h * HD + d];
                vv = g_qkvp[base + 2 * DIM + h * HD + d];
            } // else zero-padded unfold -> kv=vv=0
        }
        sk[i] = kv;
        sv[i] = vv;
    }
    __syncthreads();

    // ---- logits + bias: thread (qi = tid>>2, jg = tid&3) ----
    {
        const int qi = tid >> 2, jg = tid & 3;
        if (qi < WA) {
            float qr[HD];
#pragma unroll
            for (int d = 0; d < HD; d += 4) {
                float4 t = *(const float4*)&sq[qi * HD + d];
                qr[d] = t.x; qr[d + 1] = t.y; qr[d + 2] = t.z; qr[d + 3] = t.w;
            }
            const int rq = qi / 7, cq = qi - rq * 7;
            for (int j = jg; j < NK; j += 4) {
                float acc = 0.f;
#pragma unroll
                for (int d = 0; d < HD; d += 4) {
                    float4 kt = *(const float4*)&sk[j * HD + d];
                    acc += qr[d] * kt.x + qr[d + 1] * kt.y
                         + qr[d + 2] * kt.z + qr[d + 3] * kt.w;
                }
                float bias;
                if (j < WA) {
                    int rk = j / 7, ck = j - rk * 7;
                    int rel = (rq - rk + 6) * 13 + (cq - ck + 6);
                    bias = rpb_table[rel * HEADS + h];
                } else if (j < WA + NROLL) {
                    bias = rpb_nb[(h * WA + qi) * NROLL + (j - WA)];
                } else {
                    int jp = j - WA - NROLL;
                    int rk = jp / 7, ck = jp - rk * 7;
                    int rel = (rq - rk + 6) * 13 + (cq - ck + 6);
                    bias = rpb_win[h * 169 + rel];
                    int py = wi + rk - EXPAND, px = wj + ck - EXPAND;
                    if (py < 0 || py >= NWH || px < 0 || px >= NWW) bias -= 100.f;
                }
                sl[qi * NK + j] = acc + bias;
            }
        }
    }
    __syncthreads();

    // ---- softmax (warp per row) ----
    {
        const int warp = tid >> 5, lane = tid & 31;
        for (int row = warp; row < WA; row += 8) {
            float m = -1e30f;
            for (int j = lane; j < NK; j += 32) m = fmaxf(m, sl[row * NK + j]);
#pragma unroll
            for (int o = 16; o > 0; o >>= 1) m = fmaxf(m, __shfl_xor_sync(0xffffffffu, m, o));
            float ssum = 0.f;
            for (int j = lane; j < NK; j += 32) {
                float e = __expf(sl[row * NK + j] - m);
                sl[row * NK + j] = e;
                ssum += e;
            }
#pragma unroll
            for (int o = 16; o > 0; o >>= 1) ssum += __shfl_xor_sync(0xffffffffu, ssum, o);
            float inv = 1.f / ssum;
            for (int j = lane; j < NK; j += 32) sl[row * NK + j] *= inv;
        }
    }
    __syncthreads();

    // ---- out = attn @ v : thread (qi = tid>>2, d-block = tid&3) ----
    {
        const int qi = tid >> 2, dg = tid & 3;
        if (qi < WA) {
            const int d0 = dg << 3;
            float acc[8] = {};
            for (int j = 0; j < NK; j++) {
                float p = sl[qi * NK + j];
                float4 v0 = *(const float4*)&sv[j * HD + d0];
                float4 v1 = *(const float4*)&sv[j * HD + d0 + 4];
                acc[0] += p * v0.x; acc[1] += p * v0.y;
                acc[2] += p * v0.z; acc[3] += p * v0.w;
                acc[4] += p * v1.x; acc[5] += p * v1.y;
                acc[6] += p * v1.z; acc[7] += p * v1.w;
            }
            float* o = &g_attnout[(long)(w * WA + qi) * DIM + h * HD + d0];
            *(float4*)o       = make_float4(acc[0], acc[1], acc[2], acc[3]);
            *(float4*)(o + 4) = make_float4(acc[4], acc[5], acc[6], acc[7]);
        }
    }
}

// ============================================================
// launch
// ============================================================
extern "C" void kernel_launch(void* const* d_in, const int* in_sizes, int n_in,
                              void* d_out, int out_size) {
    const float* x         = (const float*)d_in[0];
    const float* x_pooled  = (const float*)d_in[1];
    const float* qkv_w     = (const float*)d_in[2];
    const float* qkv_b     = (const float*)d_in[3];
    const float* proj_w    = (const float*)d_in[4];
    const float* proj_b    = (const float*)d_in[5];
    const float* rpb_table = (const float*)d_in[6];
    const float* rpb_nb    = (const float*)d_in[7];
    const float* rpb_win   = (const float*)d_in[8];
    float* out = (float*)d_out;

    float *p_qkv = nullptr, *p_qkvp = nullptr, *p_ao = nullptr;
    cudaGetSymbolAddress((void**)&p_qkv,  g_qkv);
    cudaGetSymbolAddress((void**)&p_qkvp, g_qkvp);
    cudaGetSymbolAddress((void**)&p_ao,   g_attnout);

    const int attn_smem = (WA * HD + 2 * NK * HD + WA * NK) * (int)sizeof(float); // 110232
    cudaFuncSetAttribute(attn_kernel, cudaFuncAttributeMaxDynamicSharedMemorySize, attn_smem);

    init_rtab_kernel<<<1, 32>>>();

    // qkv for fine map: (100352,192) @ (192,576)^T(row-major N,K)
    gemm_bias_kernel<<<dim3(100352 / 64, QKVC / 64), 256>>>(
        x, qkv_w, qkv_b, p_qkv, BATCH * HH * WWID, QKVC, DIM);

    // qkv for pooled map: (2048,192)
    gemm_bias_kernel<<<dim3(2048 / 64, QKVC / 64), 256>>>(
        x_pooled, qkv_w, qkv_b, p_qkvp, BATCH * NWH * NWW, QKVC, DIM);

    // attention
    attn_kernel<<<dim3(BNW, HEADS), 256, attn_smem>>>(rpb_table, rpb_nb, rpb_win);

    // projection: (100352,192) @ (192,192)^T + bias
    gemm_bias_kernel<<<dim3(100352 / 64, DIM / 64), 256>>>(
        p_ao, proj_w, proj_b, out, BNW * WA, DIM, DIM);
}

// round 2
// speedup vs baseline: 1.7688x; 1.7688x over previous
#include <cuda_runtime.h>

// ---- problem constants ----
#define BATCH 8
#define HH    112
#define WWID  112
#define DIM   192
#define HEADS 6
#define HD    32
#define SKP   36               // padded k/v row stride (floats): 144B -> bank rotate 4
#define WS    7
#define WA    49
#define EXPAND 3
#define NWH   16
#define NWW   16
#define BNW   2048
#define NROLL 132
#define NK    230
#define QKVC  (3*DIM)          // 576
#define ATT_SCALE 0.17677669529663689f

// ---- scratch (device globals: allocation-free) ----
__device__ float g_qkv [BATCH*HH*WWID*QKVC];
__device__ float g_qkvp[BATCH*NWH*NWW*QKVC];
__device__ float g_attnout[BNW*WA*DIM];
__device__ int   g_rtab[NROLL];

// ============================================================
// init: rolled-ring valid-index table (VALID_ROLLED order)
// ============================================================
__global__ void init_rtab_kernel() {
    if (threadIdx.x == 0 && blockIdx.x == 0) {
        int n = 0;
        for (int s = 0; s < 4; s++)
            for (int r = 0; r < 7; r++)
                for (int c = 0; c < 7; c++) {
                    bool inval;
                    if      (s == 0) inval = (r < 4 && c < 4);
                    else if (s == 1) inval = (r < 4 && c >= 3);
                    else if (s == 2) inval = (r >= 3 && c < 4);
                    else             inval = (r >= 3 && c >= 3);
                    if (!inval) g_rtab[n++] = (s << 6) | (r << 3) | c;
                }
    }
}

// ============================================================
// GEMM: C[M,N] = A[M,K] @ Bw[N,K]^T + bias[N]
// 128x64 tile, k-chunk 16, 256 threads, 8x4 per thread.
// M % 128 == 0, N % 64 == 0, K % 16 == 0 for all call sites.
// ============================================================
__global__ __launch_bounds__(256)
void gemm_bias_kernel(const float* __restrict__ A, const float* __restrict__ Bw,
                      const float* __restrict__ bias, float* __restrict__ C,
                      int M, int N, int K) {
    __shared__ float As[16][132];
    __shared__ float Bs[16][68];
    const int tid = threadIdx.x;
    const int m0 = blockIdx.x << 7;
    const int n0 = blockIdx.y << 6;
    const int ar = tid >> 1, ac = (tid & 1) << 3;   // A: row 0..127, col 0/8
    const int br = tid >> 2, bc = (tid & 3) << 2;   // B: row 0..63,  col 0/4/8/12
    const int ty = tid >> 4, tx = tid & 15;         // out: 8 rows (ty), 4 cols (tx)

    float acc[8][4] = {};

    for (int k0 = 0; k0 < K; k0 += 16) {
        float4 a0 = *(const float4*)(A + (long)(m0 + ar) * K + k0 + ac);
        float4 a1 = *(const float4*)(A + (long)(m0 + ar) * K + k0 + ac + 4);
        float4 bv = *(const float4*)(Bw + (long)(n0 + br) * K + k0 + bc);
        As[ac + 0][ar] = a0.x; As[ac + 1][ar] = a0.y;
        As[ac + 2][ar] = a0.z; As[ac + 3][ar] = a0.w;
        As[ac + 4][ar] = a1.x; As[ac + 5][ar] = a1.y;
        As[ac + 6][ar] = a1.z; As[ac + 7][ar] = a1.w;
        Bs[bc + 0][br] = bv.x; Bs[bc + 1][br] = bv.y;
        Bs[bc + 2][br] = bv.z; Bs[bc + 3][br] = bv.w;
        __syncthreads();
#pragma unroll
        for (int kk = 0; kk < 16; kk++) {
            float4 a4 = *(const float4*)&As[kk][ty << 3];
            float4 a5 = *(const float4*)&As[kk][(ty << 3) + 4];
            float4 b4 = *(const float4*)&Bs[kk][tx << 2];
            float a[8] = {a4.x, a4.y, a4.z, a4.w, a5.x, a5.y, a5.z, a5.w};
            float b[4] = {b4.x, b4.y, b4.z, b4.w};
#pragma unroll
            for (int i = 0; i < 8; i++)
#pragma unroll
                for (int j = 0; j < 4; j++)
                    acc[i][j] += a[i] * b[j];
        }
        __syncthreads();
    }

    float4 bb = *(const float4*)(bias + n0 + (tx << 2));
#pragma unroll
    for (int i = 0; i < 8; i++) {
        float4 o;
        o.x = acc[i][0] + bb.x; o.y = acc[i][1] + bb.y;
        o.z = acc[i][2] + bb.z; o.w = acc[i][3] + bb.w;
        *(float4*)(C + (long)(m0 + (ty << 3) + i) * N + n0 + (tx << 2)) = o;
    }
}

// ============================================================
// attention: one block = one (window, head). 256 threads.
// smem: k(230x36) v(230x36) logits(49x230) = 111320 B
// ============================================================
__global__ __launch_bounds__(256)
void attn_kernel(const float* __restrict__ rpb_table,
                 const float* __restrict__ rpb_nb,
                 const float* __restrict__ rpb_win) {
    extern __shared__ float sm[];
    float* sk = sm;                    // NK*SKP
    float* sv = sk + NK * SKP;         // NK*SKP
    float* sl = sv + NK * SKP;         // WA*NK

    const int tid = threadIdx.x;
    const int w = blockIdx.x;
    const int h = blockIdx.y;
    const int b  = w >> 8;
    const int wl = w & 255;
    const int wi = wl >> 4, wj = wl & 15;
    const int y0 = wi * WS, x0 = wj * WS;

    // ---- gather k / v into padded smem ----
    for (int i = tid; i < NK * HD; i += 256) {
        int j = i >> 5, d = i & 31;
        float kv = 0.f, vv = 0.f;
        if (j < WA) {
            int r = j / 7, c = j - r * 7;
            int base = (((b * HH) + (y0 + r)) * WWID + (x0 + c)) * QKVC;
            kv = g_qkv[base + DIM     + h * HD + d];
            vv = g_qkv[base + 2 * DIM + h * HD + d];
        } else if (j < WA + NROLL) {
            int pk = g_rtab[j - WA];
            int s = pk >> 6, r = (pk >> 3) & 7, c = pk & 7;
            int dy = (s < 2) ? EXPAND : -EXPAND;
            int dx = ((s & 1) == 0) ? EXPAND : -EXPAND;
            int y = (y0 + r + dy + HH) % HH;
            int x = (x0 + c + dx + WWID) % WWID;
            int base = ((b * HH + y) * WWID + x) * QKVC;
            kv = g_qkv[base + DIM     + h * HD + d];
            vv = g_qkv[base + 2 * DIM + h * HD + d];
        } else {
            int jp = j - WA - NROLL;
            int r = jp / 7, c = jp - r * 7;
            int py = wi + r - EXPAND, px = wj + c - EXPAND;
            if (py >= 0 && py < NWH && px >= 0 && px < NWW) {
                int base = ((b * NWH + py) * NWW + px) * QKVC;
                kv = g_qkvp[base + DIM     + h * HD + d];
                vv = g_qkvp[base + 2 * DIM + h * HD + d];
            }
        }
        sk[j * SKP + d] = kv;
        sv[j * SKP + d] = vv;
    }
    __syncthreads();

    // ---- logits + bias: 2 q-rows per thread, q in registers from gmem ----
    {
        const int p  = tid >> 3;        // q-row pair 0..31 (25 used)
        const int jg = tid & 7;
        if (p < 25) {
            const int r0 = 2 * p;
            const int r1 = r0 + 1;
            const bool has2 = (r1 < WA);
            float4 qa[8], qb[8];
            {
                int rr = r0 / 7, cc = r0 - rr * 7;
                const float* qp = &g_qkv[(((b * HH) + (y0 + rr)) * WWID + (x0 + cc)) * QKVC + h * HD];
#pragma unroll
                for (int d = 0; d < 8; d++) qa[d] = *(const float4*)(qp + 4 * d);
                int r2 = has2 ? r1 : r0;
                rr = r2 / 7; cc = r2 - rr * 7;
                qp = &g_qkv[(((b * HH) + (y0 + rr)) * WWID + (x0 + cc)) * QKVC + h * HD];
#pragma unroll
                for (int d = 0; d < 8; d++) qb[d] = *(const float4*)(qp + 4 * d);
            }
            const int rq0 = r0 / 7, cq0 = r0 - rq0 * 7;
            const int rq1 = r1 / 7, cq1 = r1 - rq1 * 7;

            for (int j = jg; j < NK; j += 8) {
                float acc0 = 0.f, acc1 = 0.f;
#pragma unroll
                for (int d = 0; d < 8; d++) {
                    float4 kt = *(const float4*)&sk[j * SKP + 4 * d];
                    acc0 += qa[d].x * kt.x + qa[d].y * kt.y + qa[d].z * kt.z + qa[d].w * kt.w;
                    acc1 += qb[d].x * kt.x + qb[d].y * kt.y + qb[d].z * kt.z + qb[d].w * kt.w;
                }
                float b0, b1;
                if (j < WA) {
                    int rk = j / 7, ck = j - rk * 7;
                    b0 = rpb_table[((rq0 - rk + 6) * 13 + (cq0 - ck + 6)) * HEADS + h];
                    b1 = rpb_table[((rq1 - rk + 6) * 13 + (cq1 - ck + 6)) * HEADS + h];
                } else if (j < WA + NROLL) {
                    b0 = rpb_nb[(h * WA + r0) * NROLL + (j - WA)];
                    b1 = has2 ? rpb_nb[(h * WA + r1) * NROLL + (j - WA)] : 0.f;
                } else {
                    int jp = j - WA - NROLL;
                    int rk = jp / 7, ck = jp - rk * 7;
                    b0 = rpb_win[h * 169 + (rq0 - rk + 6) * 13 + (cq0 - ck + 6)];
                    b1 = has2 ? rpb_win[h * 169 + (rq1 - rk + 6) * 13 + (cq1 - ck + 6)] : 0.f;
                    int py = wi + rk - EXPAND, px = wj + ck - EXPAND;
                    if (py < 0 || py >= NWH || px < 0 || px >= NWW) { b0 -= 100.f; b1 -= 100.f; }
                }
                sl[r0 * NK + j] = acc0 * ATT_SCALE + b0;
                if (has2) sl[r1 * NK + j] = acc1 * ATT_SCALE + b1;
            }
        }
    }
    __syncthreads();

    // ---- softmax (warp per row) ----
    {
        const int warp = tid >> 5, lane = tid & 31;
        for (int row = warp; row < WA; row += 8) {
            float m = -1e30f;
            for (int j = lane; j < NK; j += 32) m = fmaxf(m, sl[row * NK + j]);
#pragma unroll
            for (int o = 16; o > 0; o >>= 1) m = fmaxf(m, __shfl_xor_sync(0xffffffffu, m, o));
            float ssum = 0.f;
            for (int j = lane; j < NK; j += 32) {
                float e = __expf(sl[row * NK + j] - m);
                sl[row * NK + j] = e;
                ssum += e;
            }
#pragma unroll
            for (int o = 16; o > 0; o >>= 1) ssum += __shfl_xor_sync(0xffffffffu, ssum, o);
            float inv = 1.f / ssum;
            for (int j = lane; j < NK; j += 32) sl[row * NK + j] *= inv;
        }
    }
    __syncthreads();

    // ---- out = attn @ v : 4 q-rows x 4 d per thread ----
    {
        const int g  = tid >> 3;        // row group 0..31 (13 used)
        const int dg = tid & 7;
        if (g < 13) {
            const int r0 = 4 * g;
            const int rmax = (WA - r0 < 4) ? (WA - r0) : 4;
            const int d0 = dg << 2;
            float acc[4][4] = {};
            for (int j = 0; j < NK; j++) {
                float4 v4 = *(const float4*)&sv[j * SKP + d0];
                float pr[4];
#pragma unroll
                for (int i = 0; i < 4; i++)
                    pr[i] = (i < rmax) ? sl[(r0 + i) * NK + j] : 0.f;
#pragma unroll
                for (int i = 0; i < 4; i++) {
                    acc[i][0] += pr[i] * v4.x; acc[i][1] += pr[i] * v4.y;
                    acc[i][2] += pr[i] * v4.z; acc[i][3] += pr[i] * v4.w;
                }
            }
#pragma unroll
            for (int i = 0; i < 4; i++) {
                if (i < rmax) {
                    float* o = &g_attnout[(long)(w * WA + r0 + i) * DIM + h * HD + d0];
                    *(float4*)o = make_float4(acc[i][0], acc[i][1], acc[i][2], acc[i][3]);
                }
            }
        }
    }
}

// ============================================================
// launch
// ============================================================
extern "C" void kernel_launch(void* const* d_in, const int* in_sizes, int n_in,
                              void* d_out, int out_size) {
    const float* x         = (const float*)d_in[0];
    const float* x_pooled  = (const float*)d_in[1];
    const float* qkv_w     = (const float*)d_in[2];
    const float* qkv_b     = (const float*)d_in[3];
    const float* proj_w    = (const float*)d_in[4];
    const float* proj_b    = (const float*)d_in[5];
    const float* rpb_table = (const float*)d_in[6];
    const float* rpb_nb    = (const float*)d_in[7];
    const float* rpb_win   = (const float*)d_in[8];
    float* out = (float*)d_out;

    float *p_qkv = nullptr, *p_qkvp = nullptr, *p_ao = nullptr;
    cudaGetSymbolAddress((void**)&p_qkv,  g_qkv);
    cudaGetSymbolAddress((void**)&p_qkvp, g_qkvp);
    cudaGetSymbolAddress((void**)&p_ao,   g_attnout);

    const int attn_smem = (2 * NK * SKP + WA * NK) * (int)sizeof(float); // 111320
    cudaFuncSetAttribute(attn_kernel, cudaFuncAttributeMaxDynamicSharedMemorySize, attn_smem);

    init_rtab_kernel<<<1, 32>>>();

    // qkv fine: (100352,576) = x(100352,192) @ qkv_w(576,192)^T
    gemm_bias_kernel<<<dim3(100352 / 128, QKVC / 64), 256>>>(
        x, qkv_w, qkv_b, p_qkv, BATCH * HH * WWID, QKVC, DIM);

    // qkv pooled: (2048,576)
    gemm_bias_kernel<<<dim3(2048 / 128, QKVC / 64), 256>>>(
        x_pooled, qkv_w, qkv_b, p_qkvp, BATCH * NWH * NWW, QKVC, DIM);

    // attention
    attn_kernel<<<dim3(BNW, HEADS), 256, attn_smem>>>(rpb_table, rpb_nb, rpb_win);

    // projection: (100352,192) @ proj_w(192,192)^T
    gemm_bias_kernel<<<dim3(100352 / 128, DIM / 64), 256>>>(
        p_ao, proj_w, proj_b, out, BNW * WA, DIM, DIM);
}